// round 14
// baseline (speedup 1.0000x reference)
#include <cuda_runtime.h>
#include <cuda_bf16.h>
#include <mma.h>
#include <cstdint>

using namespace nvcuda;

// Problem constants
#define Bn   16
#define Ln   512
#define DBn  3072
#define Dn   300
#define NNn  256
#define NWn  30
#define Hn   256

#define Mtot (Bn * Ln)          // 8192
#define NPAD 320
#define NODES (Bn * NNn)        // 4096
#define KPH  320

// Main GEMM tiling
#define GBM 128
#define GBN 160
#define GBK 32
#define KP  40                  // smem pitch in bf16 (80 B)
#define NKT (DBn / GBK)         // 96

// ---------------------------------------------------------------------------
// Single static scratch, 15.4 MB (proven-safe)
// ---------------------------------------------------------------------------
#define OFF_ART  0
#define OFF_U    9830400
#define OFF_W1   (OFF_U + 5242880)
#define OFF_PART (OFF_W1 + 327680)
#define SCRATCH_BYTES (OFF_PART + 32768)

__device__ __align__(256) unsigned char g_scratch[SCRATCH_BYTES];

#define P_ART  ((float*)(g_scratch + OFF_ART))
#define P_WHI  ((__nv_bfloat16*)(g_scratch + OFF_U))
#define P_WLO  ((__nv_bfloat16*)(g_scratch + OFF_U + 1966080))
#define P_PHI  ((__nv_bfloat16*)(g_scratch + OFF_U))
#define P_PLO  ((__nv_bfloat16*)(g_scratch + OFF_U + 2621440))
#define P_W1HI ((__nv_bfloat16*)(g_scratch + OFF_W1))
#define P_W1LO ((__nv_bfloat16*)(g_scratch + OFF_W1 + 163840))
#define P_PART ((float*)(g_scratch + OFF_PART))

__device__ __forceinline__ void cp_async16(uint32_t dst, const void* src) {
    asm volatile("cp.async.cg.shared.global [%0], [%1], 16;" :: "r"(dst), "l"(src));
}
__device__ __forceinline__ uint32_t smem_u32(const void* p) {
    uint32_t a;
    asm("{ .reg .u64 t; cvta.to.shared.u64 t, %1; cvt.u32.u64 %0, t; }" : "=r"(a) : "l"(p));
    return a;
}
__device__ __forceinline__ void split2(float x0, float x1, uint32_t& h, uint32_t& l) {
    __nv_bfloat162 hh = __float22bfloat162_rn(make_float2(x0, x1));
    h = *(uint32_t*)&hh;
    float h0 = __uint_as_float(h << 16);
    float h1 = __uint_as_float(h & 0xffff0000u);
    __nv_bfloat162 ll = __float22bfloat162_rn(make_float2(x0 - h0, x1 - h1));
    l = *(uint32_t*)&ll;
}

// ---------------------------------------------------------------------------
// Kernel 0: split W_bert [->320x3072] and W1 [->256x320] in one launch
// ---------------------------------------------------------------------------
#define NWP4  (NPAD * DBn / 4)          // 245760
#define NW1P4 (Hn * KPH / 4)            // 20480

__global__ __launch_bounds__(256) void split_weights_kernel(
    const float* __restrict__ W, const float* __restrict__ W1)
{
    int i = blockIdx.x * 256 + threadIdx.x;
    if (i < NWP4) {
        int row = (i * 4) / DBn;
        float4 v = make_float4(0.f, 0.f, 0.f, 0.f);
        if (row < Dn) v = reinterpret_cast<const float4*>(W)[i];
        uint32_t h01, l01, h23, l23;
        split2(v.x, v.y, h01, l01);
        split2(v.z, v.w, h23, l23);
        reinterpret_cast<uint2*>(P_WHI)[i] = make_uint2(h01, h23);
        reinterpret_cast<uint2*>(P_WLO)[i] = make_uint2(l01, l23);
    } else if (i < NWP4 + NW1P4) {
        int j = i - NWP4;
        int row = j / (KPH / 4);
        int c4  = j % (KPH / 4);
        float4 v = make_float4(0.f, 0.f, 0.f, 0.f);
        if (c4 < Dn / 4)
            v = reinterpret_cast<const float4*>(W1)[row * (Dn / 4) + c4];
        uint32_t h01, l01, h23, l23;
        split2(v.x, v.y, h01, l01);
        split2(v.z, v.w, h23, l23);
        reinterpret_cast<uint2*>(P_W1HI)[j] = make_uint2(h01, h23);
        reinterpret_cast<uint2*>(P_W1LO)[j] = make_uint2(l01, l23);
    }
}

// ---------------------------------------------------------------------------
// Kernel 1: fused A-split + wmma bf16 3-pass GEMM + bias + PReLU -> art
// R11 config + warp-uniform jmax to skip pure-padding fragment columns
// ---------------------------------------------------------------------------
#define ASUB 10240
#define WSUB 12800
#define SM_A 0
#define SM_W (4 * ASUB)
#define SMEMG (SM_W + 4 * WSUB)     // 92160

__global__ __launch_bounds__(256) void gemm_fused3_kernel(
    const float* __restrict__ A,
    const float* __restrict__ bias,
    const float* __restrict__ prelu_a)
{
    extern __shared__ char smem[];
    const uint32_t sb = smem_u32(smem);
    const int tid = threadIdx.x;
    const int wid = tid >> 5;
    const int m0 = blockIdx.y * GBM;
    const int n0 = blockIdx.x * GBN;
    const int wm = wid >> 1;
    const int wn = wid & 1;

    // warp-uniform fragment-column count: skip frags entirely in pad cols >=300
    const int nlim = Dn - n0 - wn * 80;                    // cols this warp must cover
    const int jmax = (nlim >= 80) ? 5 : ((nlim + 15) >> 4); // 5 except tile1/wn1 -> 4

    const int arow = tid >> 1;
    const int ahalf = tid & 1;
    const float* aptr = A + (size_t)(m0 + arow) * DBn + ahalf * 16;

    wmma::fragment<wmma::accumulator, 16, 16, 16, float> acc[2][5];
    #pragma unroll
    for (int i = 0; i < 2; i++)
        #pragma unroll
        for (int j = 0; j < 5; j++) wmma::fill_fragment(acc[i][j], 0.0f);

    auto cp_w_stage = [&](int t, int buf) {
        const int k0 = t * GBK;
        #pragma unroll
        for (int hl = 0; hl < 2; hl++) {
            const __nv_bfloat16* src = hl ? P_WLO : P_WHI;
            uint32_t dst = sb + SM_W + (uint32_t)((buf * 2 + hl) * WSUB);
            #pragma unroll
            for (int r = 0; r < 3; r++) {
                int i = tid + r * 256;
                if (i < 640) {
                    int row = i >> 2, seg = i & 3;
                    cp_async16(dst + (uint32_t)(row * (KP * 2) + seg * 16),
                               src + (size_t)(n0 + row) * DBn + k0 + seg * 8);
                }
            }
        }
        asm volatile("cp.async.commit_group;");
    };

    auto convert_a = [&](const float4* aR, int buf) {
        uint32_t ph[8], pl[8];
        const float* af = (const float*)aR;
        #pragma unroll
        for (int q = 0; q < 8; q++)
            split2(af[2 * q], af[2 * q + 1], ph[q], pl[q]);
        uint4* dh = (uint4*)(smem + SM_A + (buf * 2 + 0) * ASUB);
        uint4* dl = (uint4*)(smem + SM_A + (buf * 2 + 1) * ASUB);
        const int off16 = (arow * (KP * 2) + ahalf * 32) >> 4;
        dh[off16 + 0] = make_uint4(ph[0], ph[1], ph[2], ph[3]);
        dh[off16 + 1] = make_uint4(ph[4], ph[5], ph[6], ph[7]);
        dl[off16 + 0] = make_uint4(pl[0], pl[1], pl[2], pl[3]);
        dl[off16 + 1] = make_uint4(pl[4], pl[5], pl[6], pl[7]);
    };

    float4 aR[4];
    #pragma unroll
    for (int q = 0; q < 4; q++) aR[q] = ((const float4*)aptr)[q];
    cp_w_stage(0, 0);
    convert_a(aR, 0);
    {
        const float* ap = aptr + GBK;
        #pragma unroll
        for (int q = 0; q < 4; q++) aR[q] = ((const float4*)ap)[q];
    }
    asm volatile("cp.async.wait_group 0;");
    __syncthreads();

    for (int t = 0; t < NKT; t++) {
        const int b = t & 1;
        if (t + 1 < NKT) cp_w_stage(t + 1, b ^ 1);

        {
            const __nv_bfloat16* sAhi = (const __nv_bfloat16*)(smem + SM_A + (b * 2 + 0) * ASUB);
            const __nv_bfloat16* sAlo = (const __nv_bfloat16*)(smem + SM_A + (b * 2 + 1) * ASUB);
            const __nv_bfloat16* sWhi = (const __nv_bfloat16*)(smem + SM_W + (b * 2 + 0) * WSUB);
            const __nv_bfloat16* sWlo = (const __nv_bfloat16*)(smem + SM_W + (b * 2 + 1) * WSUB);
            #pragma unroll
            for (int kk = 0; kk < GBK; kk += 16) {
                wmma::fragment<wmma::matrix_a, 16, 16, 16, __nv_bfloat16, wmma::row_major> ah[2], al[2];
                #pragma unroll
                for (int i = 0; i < 2; i++) {
                    const int mo = (wm * 32 + i * 16) * KP + kk;
                    wmma::load_matrix_sync(ah[i], sAhi + mo, KP);
                    wmma::load_matrix_sync(al[i], sAlo + mo, KP);
                }
                #pragma unroll
                for (int j = 0; j < 5; j++) {
                    if (j < jmax) {     // warp-uniform: skip all-padding frag cols
                        wmma::fragment<wmma::matrix_b, 16, 16, 16, __nv_bfloat16, wmma::col_major> bh, bl;
                        const int no = (wn * 80 + j * 16) * KP + kk;
                        wmma::load_matrix_sync(bh, sWhi + no, KP);
                        wmma::load_matrix_sync(bl, sWlo + no, KP);
                        #pragma unroll
                        for (int i = 0; i < 2; i++) {
                            wmma::mma_sync(acc[i][j], ah[i], bh, acc[i][j]);
                            wmma::mma_sync(acc[i][j], ah[i], bl, acc[i][j]);
                            wmma::mma_sync(acc[i][j], al[i], bh, acc[i][j]);
                        }
                    }
                }
            }
        }

        if (t + 1 < NKT) {
            convert_a(aR, b ^ 1);
            if (t + 2 < NKT) {
                const float* ap = aptr + (size_t)(t + 2) * GBK;
                #pragma unroll
                for (int q = 0; q < 4; q++) aR[q] = ((const float4*)ap)[q];
            }
            asm volatile("cp.async.wait_group 0;");
        }
        __syncthreads();
    }

    float* ep = (float*)smem;   // 128 x 160
    #pragma unroll
    for (int j = 0; j < 5; j++)
        if (j < jmax)
            #pragma unroll
            for (int i = 0; i < 2; i++)
                wmma::store_matrix_sync(ep + (wm * 32 + i * 16) * 160 + wn * 80 + j * 16,
                                        acc[i][j], 160, wmma::mem_row_major);
    __syncthreads();

    const float pa = prelu_a[0];
    float* art = P_ART;
    for (int e = tid; e < GBM * GBN; e += 256) {
        int m = e / GBN, n = e % GBN;
        int gn = n0 + n;
        if (gn < Dn) {
            float v = ep[e] + bias[gn];
            v = (v > 0.f) ? v : pa * v;
            art[(size_t)(m0 + m) * Dn + gn] = v;
        }
    }
}

// ---------------------------------------------------------------------------
// Kernel 2: pooling, compacted words + float4 gather -> bf16 hi/lo [4096,320]
// ---------------------------------------------------------------------------
__global__ __launch_bounds__(128) void pool_kernel(
    const int* __restrict__ nodes_idx,
    const int* __restrict__ nmask)
{
    __shared__ int   s_tmp_idx[NWn];
    __shared__ int   s_tmp_msk[NWn];
    __shared__ int   s_off[NWn];
    __shared__ int   s_cw;
    __shared__ float s_inv;

    const int node = blockIdx.x;
    const int b    = node >> 8;
    const int tid  = threadIdx.x;

    if (tid < NWn) {
        int base = node * NWn + tid;
        s_tmp_idx[tid] = nodes_idx[base];
        s_tmp_msk[tid] = nmask[base];
    }
    __syncthreads();
    if (tid == 0) {
        int cw = 0;
        #pragma unroll
        for (int w = 0; w < NWn; w++)
            if (s_tmp_msk[w]) s_off[cw++] = s_tmp_idx[w] * (Dn / 4);
        s_cw = cw;
        s_inv = 1.0f / fmaxf((float)cw, 1.0f);
    }
    __syncthreads();

    const float4* art4 = (const float4*)(P_ART + (size_t)b * Ln * Dn);
    __nv_bfloat16* phi = P_PHI + (size_t)node * KPH;
    __nv_bfloat16* plo = P_PLO + (size_t)node * KPH;
    const int cw = s_cw;
    const float inv = s_inv;

    if (tid < Dn / 4) {
        float4 s = make_float4(0.f, 0.f, 0.f, 0.f);
        #pragma unroll 5
        for (int j = 0; j < cw; j++) {
            float4 v = art4[s_off[j] + tid];
            s.x += v.x; s.y += v.y; s.z += v.z; s.w += v.w;
        }
        s.x *= inv; s.y *= inv; s.z *= inv; s.w *= inv;
        uint32_t h01, l01, h23, l23;
        split2(s.x, s.y, h01, l01);
        split2(s.z, s.w, h23, l23);
        *(uint2*)(phi + tid * 4) = make_uint2(h01, h23);
        *(uint2*)(plo + tid * 4) = make_uint2(l01, l23);
    } else if (tid < KPH / 4) {
        *(uint2*)(phi + tid * 4) = make_uint2(0u, 0u);
        *(uint2*)(plo + tid * 4) = make_uint2(0u, 0u);
    }
}

// ---------------------------------------------------------------------------
// Kernel 3: head GEMM, M-tile 64 -> 128 CTAs. Warp tile 16x64 (4 frags).
// h = relu(pooled·W1^T + b1); W2-dot fused into epilogue partial.
// ---------------------------------------------------------------------------
#define HASUB 5120                  // 64*40*2
#define HBSUB 10240                 // 128*40*2
#define HSM_A 0
#define HSM_B (4 * HASUB)           // 20480
#define SMEMG2 (HSM_B + 4 * HBSUB)  // 61440 (epilogue 64x128 f32 = 32768 overlays)
#define NKT2 (KPH / 32)             // 10

__global__ __launch_bounds__(256) void head_gemm_kernel(
    const float* __restrict__ b1,
    const float* __restrict__ W2)
{
    extern __shared__ char smem[];
    const uint32_t sb = smem_u32(smem);
    const int tid = threadIdx.x;
    const int wid = tid >> 5;
    const int m0 = blockIdx.y * 64;       // node tile (64 rows)
    const int n0 = blockIdx.x * 128;      // hidden tile
    const int wm = wid >> 1;              // 0..3 -> 16-row slices
    const int wn = wid & 1;               // 0..1 -> 64-col slices

    wmma::fragment<wmma::accumulator, 16, 16, 16, float> acc[4];
    #pragma unroll
    for (int j = 0; j < 4; j++) wmma::fill_fragment(acc[j], 0.0f);

    auto cp_stage = [&](int t, int buf) {
        const int k0 = t * 32;
        #pragma unroll
        for (int hl = 0; hl < 2; hl++) {
            const __nv_bfloat16* srcA = hl ? P_PLO : P_PHI;
            const __nv_bfloat16* srcB = hl ? P_W1LO : P_W1HI;
            uint32_t dA = sb + HSM_A + (uint32_t)((buf * 2 + hl) * HASUB);
            uint32_t dB = sb + HSM_B + (uint32_t)((buf * 2 + hl) * HBSUB);
            {   // A: 64 rows x 4 segs = 256 chunks, 1 per thread
                int row = tid >> 2, seg = tid & 3;
                cp_async16(dA + (uint32_t)(row * (KP * 2) + seg * 16),
                           srcA + (size_t)(m0 + row) * KPH + k0 + seg * 8);
            }
            #pragma unroll
            for (int r = 0; r < 2; r++) {   // B: 128 rows x 4 segs = 512 chunks
                int i = tid + r * 256;
                int row = i >> 2, seg = i & 3;
                cp_async16(dB + (uint32_t)(row * (KP * 2) + seg * 16),
                           srcB + (size_t)(n0 + row) * KPH + k0 + seg * 8);
            }
        }
        asm volatile("cp.async.commit_group;");
    };

    cp_stage(0, 0);
    asm volatile("cp.async.wait_group 0;");
    __syncthreads();

    for (int t = 0; t < NKT2; t++) {
        const int b = t & 1;
        if (t + 1 < NKT2) cp_stage(t + 1, b ^ 1);

        {
            const __nv_bfloat16* sAhi = (const __nv_bfloat16*)(smem + HSM_A + (b * 2 + 0) * HASUB);
            const __nv_bfloat16* sAlo = (const __nv_bfloat16*)(smem + HSM_A + (b * 2 + 1) * HASUB);
            const __nv_bfloat16* sBhi = (const __nv_bfloat16*)(smem + HSM_B + (b * 2 + 0) * HBSUB);
            const __nv_bfloat16* sBlo = (const __nv_bfloat16*)(smem + HSM_B + (b * 2 + 1) * HBSUB);
            #pragma unroll
            for (int kk = 0; kk < 32; kk += 16) {
                wmma::fragment<wmma::matrix_a, 16, 16, 16, __nv_bfloat16, wmma::row_major> ah, al;
                const int mo = (wm * 16) * KP + kk;
                wmma::load_matrix_sync(ah, sAhi + mo, KP);
                wmma::load_matrix_sync(al, sAlo + mo, KP);
                #pragma unroll
                for (int j = 0; j < 4; j++) {
                    wmma::fragment<wmma::matrix_b, 16, 16, 16, __nv_bfloat16, wmma::col_major> bh, bl;
                    const int no = (wn * 64 + j * 16) * KP + kk;
                    wmma::load_matrix_sync(bh, sBhi + no, KP);
                    wmma::load_matrix_sync(bl, sBlo + no, KP);
                    wmma::mma_sync(acc[j], ah, bh, acc[j]);
                    wmma::mma_sync(acc[j], ah, bl, acc[j]);
                    wmma::mma_sync(acc[j], al, bh, acc[j]);
                }
            }
        }

        if (t + 1 < NKT2) asm volatile("cp.async.wait_group 0;");
        __syncthreads();
    }

    // epilogue: partial[m] = sum_n relu(h + b1) * W2 over this 128-col tile
    float* ep = (float*)smem;   // 64 x 128
    #pragma unroll
    for (int j = 0; j < 4; j++)
        wmma::store_matrix_sync(ep + (wm * 16) * 128 + wn * 64 + j * 16,
                                acc[j], 128, wmma::mem_row_major);
    __syncthreads();

    const int warp = tid >> 5, lane = tid & 31;
    float* part = P_PART + (size_t)blockIdx.x * NODES;
    for (int r = warp; r < 64; r += 8) {
        float s = 0.f;
        #pragma unroll
        for (int q = 0; q < 4; q++) {
            int n = lane + q * 32;
            float v = fmaxf(ep[r * 128 + n] + b1[n0 + n], 0.f);
            s += v * W2[n0 + n];
        }
        #pragma unroll
        for (int o = 16; o > 0; o >>= 1) s += __shfl_down_sync(0xffffffffu, s, o);
        if (lane == 0) part[m0 + r] = s;
    }
}

// ---------------------------------------------------------------------------
// Kernel 4: out[n] = part0[n] + part1[n] + b2
// ---------------------------------------------------------------------------
__global__ __launch_bounds__(256) void final_kernel(
    const float* __restrict__ b2, float* __restrict__ out)
{
    int n = blockIdx.x * 256 + threadIdx.x;
    if (n < NODES) out[n] = P_PART[n] + P_PART[NODES + n] + b2[0];
}

// ---------------------------------------------------------------------------
extern "C" void kernel_launch(void* const* d_in, const int* in_sizes, int n_in,
                              void* d_out, int out_size)
{
    const float* articles  = (const float*)d_in[0];
    const int*   nodes_idx = (const int*)  d_in[1];
    const int*   nmask     = (const int*)  d_in[2];
    // d_in[3], d_in[4] (relations) unused: reference discards edges
    const float* W_bert    = (const float*)d_in[5];
    const float* b_bert    = (const float*)d_in[6];
    const float* prelu_a   = (const float*)d_in[7];
    const float* W1        = (const float*)d_in[8];
    const float* b1        = (const float*)d_in[9];
    const float* W2        = (const float*)d_in[10];
    const float* b2        = (const float*)d_in[11];
    float*       out       = (float*)d_out;

    cudaFuncSetAttribute(gemm_fused3_kernel,
                         cudaFuncAttributeMaxDynamicSharedMemorySize, SMEMG);
    cudaFuncSetAttribute(head_gemm_kernel,
                         cudaFuncAttributeMaxDynamicSharedMemorySize, SMEMG2);

    // Stage 0: both weight splits in one launch
    split_weights_kernel<<<(NWP4 + NW1P4 + 255) / 256, 256>>>(W_bert, W1);

    // Stage 1: projection GEMM (jmax padding skip), one wave
    dim3 gridG(NPAD / GBN, Mtot / GBM);   // (2, 64)
    gemm_fused3_kernel<<<gridG, 256, SMEMG>>>(articles, b_bert, prelu_a);

    // Stage 2: pooling (compacted + float4) -> bf16 hi/lo
    pool_kernel<<<NODES, 128>>>(nodes_idx, nmask);

    // Stage 3: head GEMM, 128 CTAs, fused W2 partial reduction
    dim3 gridH(Hn / 128, NODES / 64);     // (2, 64)
    head_gemm_kernel<<<gridH, 256, SMEMG2>>>(b1, W2);

    // Stage 4: combine partials
    final_kernel<<<(NODES + 255) / 256, 256>>>(b2, out);
}

// round 15
// speedup vs baseline: 1.0626x; 1.0626x over previous
#include <cuda_runtime.h>
#include <cuda_bf16.h>
#include <mma.h>
#include <cstdint>

using namespace nvcuda;

// Problem constants
#define Bn   16
#define Ln   512
#define DBn  3072
#define Dn   300
#define NNn  256
#define NWn  30
#define Hn   256

#define Mtot (Bn * Ln)          // 8192
#define NPAD 320
#define NODES (Bn * NNn)        // 4096
#define KPH  320

// Main GEMM tiling
#define GBM 128
#define GBN 160
#define GBK 32
#define KP  40                  // smem pitch in bf16 (80 B)
#define NKT (DBn / GBK)         // 96

// ---------------------------------------------------------------------------
// Single static scratch, 15.4 MB (proven-safe)
// ---------------------------------------------------------------------------
#define OFF_ART  0
#define OFF_U    9830400
#define OFF_W1   (OFF_U + 5242880)
#define OFF_PART (OFF_W1 + 327680)
#define SCRATCH_BYTES (OFF_PART + 32768)

__device__ __align__(256) unsigned char g_scratch[SCRATCH_BYTES];

#define P_ART  ((float*)(g_scratch + OFF_ART))
#define P_WHI  ((__nv_bfloat16*)(g_scratch + OFF_U))
#define P_WLO  ((__nv_bfloat16*)(g_scratch + OFF_U + 1966080))
#define P_PHI  ((__nv_bfloat16*)(g_scratch + OFF_U))
#define P_PLO  ((__nv_bfloat16*)(g_scratch + OFF_U + 2621440))
#define P_W1HI ((__nv_bfloat16*)(g_scratch + OFF_W1))
#define P_W1LO ((__nv_bfloat16*)(g_scratch + OFF_W1 + 163840))
#define P_PART ((float*)(g_scratch + OFF_PART))

__device__ __forceinline__ void cp_async16(uint32_t dst, const void* src) {
    asm volatile("cp.async.cg.shared.global [%0], [%1], 16;" :: "r"(dst), "l"(src));
}
__device__ __forceinline__ uint32_t smem_u32(const void* p) {
    uint32_t a;
    asm("{ .reg .u64 t; cvta.to.shared.u64 t, %1; cvt.u32.u64 %0, t; }" : "=r"(a) : "l"(p));
    return a;
}
__device__ __forceinline__ void split2(float x0, float x1, uint32_t& h, uint32_t& l) {
    __nv_bfloat162 hh = __float22bfloat162_rn(make_float2(x0, x1));
    h = *(uint32_t*)&hh;
    float h0 = __uint_as_float(h << 16);
    float h1 = __uint_as_float(h & 0xffff0000u);
    __nv_bfloat162 ll = __float22bfloat162_rn(make_float2(x0 - h0, x1 - h1));
    l = *(uint32_t*)&ll;
}

// ---------------------------------------------------------------------------
// Kernel 0: split W_bert [->320x3072] and W1 [->256x320] in one launch
// ---------------------------------------------------------------------------
#define NWP4  (NPAD * DBn / 4)          // 245760
#define NW1P4 (Hn * KPH / 4)            // 20480

__global__ __launch_bounds__(256) void split_weights_kernel(
    const float* __restrict__ W, const float* __restrict__ W1)
{
    int i = blockIdx.x * 256 + threadIdx.x;
    if (i < NWP4) {
        int row = (i * 4) / DBn;
        float4 v = make_float4(0.f, 0.f, 0.f, 0.f);
        if (row < Dn) v = reinterpret_cast<const float4*>(W)[i];
        uint32_t h01, l01, h23, l23;
        split2(v.x, v.y, h01, l01);
        split2(v.z, v.w, h23, l23);
        reinterpret_cast<uint2*>(P_WHI)[i] = make_uint2(h01, h23);
        reinterpret_cast<uint2*>(P_WLO)[i] = make_uint2(l01, l23);
    } else if (i < NWP4 + NW1P4) {
        int j = i - NWP4;
        int row = j / (KPH / 4);
        int c4  = j % (KPH / 4);
        float4 v = make_float4(0.f, 0.f, 0.f, 0.f);
        if (c4 < Dn / 4)
            v = reinterpret_cast<const float4*>(W1)[row * (Dn / 4) + c4];
        uint32_t h01, l01, h23, l23;
        split2(v.x, v.y, h01, l01);
        split2(v.z, v.w, h23, l23);
        reinterpret_cast<uint2*>(P_W1HI)[j] = make_uint2(h01, h23);
        reinterpret_cast<uint2*>(P_W1LO)[j] = make_uint2(l01, l23);
    }
}

// ---------------------------------------------------------------------------
// Kernel 1: fused A-split + wmma bf16 3-pass GEMM + bias + PReLU -> art
// (EXACT R11/R13 branch-free config — 192us proven)
// ---------------------------------------------------------------------------
#define ASUB 10240
#define WSUB 12800
#define SM_A 0
#define SM_W (4 * ASUB)
#define SMEMG (SM_W + 4 * WSUB)     // 92160

__global__ __launch_bounds__(256) void gemm_fused3_kernel(
    const float* __restrict__ A,
    const float* __restrict__ bias,
    const float* __restrict__ prelu_a)
{
    extern __shared__ char smem[];
    const uint32_t sb = smem_u32(smem);
    const int tid = threadIdx.x;
    const int wid = tid >> 5;
    const int m0 = blockIdx.y * GBM;
    const int n0 = blockIdx.x * GBN;
    const int wm = wid >> 1;
    const int wn = wid & 1;

    const int arow = tid >> 1;
    const int ahalf = tid & 1;
    const float* aptr = A + (size_t)(m0 + arow) * DBn + ahalf * 16;

    wmma::fragment<wmma::accumulator, 16, 16, 16, float> acc[2][5];
    #pragma unroll
    for (int i = 0; i < 2; i++)
        #pragma unroll
        for (int j = 0; j < 5; j++) wmma::fill_fragment(acc[i][j], 0.0f);

    auto cp_w_stage = [&](int t, int buf) {
        const int k0 = t * GBK;
        #pragma unroll
        for (int hl = 0; hl < 2; hl++) {
            const __nv_bfloat16* src = hl ? P_WLO : P_WHI;
            uint32_t dst = sb + SM_W + (uint32_t)((buf * 2 + hl) * WSUB);
            #pragma unroll
            for (int r = 0; r < 3; r++) {
                int i = tid + r * 256;
                if (i < 640) {
                    int row = i >> 2, seg = i & 3;
                    cp_async16(dst + (uint32_t)(row * (KP * 2) + seg * 16),
                               src + (size_t)(n0 + row) * DBn + k0 + seg * 8);
                }
            }
        }
        asm volatile("cp.async.commit_group;");
    };

    auto convert_a = [&](const float4* aR, int buf) {
        uint32_t ph[8], pl[8];
        const float* af = (const float*)aR;
        #pragma unroll
        for (int q = 0; q < 8; q++)
            split2(af[2 * q], af[2 * q + 1], ph[q], pl[q]);
        uint4* dh = (uint4*)(smem + SM_A + (buf * 2 + 0) * ASUB);
        uint4* dl = (uint4*)(smem + SM_A + (buf * 2 + 1) * ASUB);
        const int off16 = (arow * (KP * 2) + ahalf * 32) >> 4;
        dh[off16 + 0] = make_uint4(ph[0], ph[1], ph[2], ph[3]);
        dh[off16 + 1] = make_uint4(ph[4], ph[5], ph[6], ph[7]);
        dl[off16 + 0] = make_uint4(pl[0], pl[1], pl[2], pl[3]);
        dl[off16 + 1] = make_uint4(pl[4], pl[5], pl[6], pl[7]);
    };

    float4 aR[4];
    #pragma unroll
    for (int q = 0; q < 4; q++) aR[q] = ((const float4*)aptr)[q];
    cp_w_stage(0, 0);
    convert_a(aR, 0);
    {
        const float* ap = aptr + GBK;
        #pragma unroll
        for (int q = 0; q < 4; q++) aR[q] = ((const float4*)ap)[q];
    }
    asm volatile("cp.async.wait_group 0;");
    __syncthreads();

    for (int t = 0; t < NKT; t++) {
        const int b = t & 1;
        if (t + 1 < NKT) cp_w_stage(t + 1, b ^ 1);

        {
            const __nv_bfloat16* sAhi = (const __nv_bfloat16*)(smem + SM_A + (b * 2 + 0) * ASUB);
            const __nv_bfloat16* sAlo = (const __nv_bfloat16*)(smem + SM_A + (b * 2 + 1) * ASUB);
            const __nv_bfloat16* sWhi = (const __nv_bfloat16*)(smem + SM_W + (b * 2 + 0) * WSUB);
            const __nv_bfloat16* sWlo = (const __nv_bfloat16*)(smem + SM_W + (b * 2 + 1) * WSUB);
            #pragma unroll
            for (int kk = 0; kk < GBK; kk += 16) {
                wmma::fragment<wmma::matrix_a, 16, 16, 16, __nv_bfloat16, wmma::row_major> ah[2], al[2];
                #pragma unroll
                for (int i = 0; i < 2; i++) {
                    const int mo = (wm * 32 + i * 16) * KP + kk;
                    wmma::load_matrix_sync(ah[i], sAhi + mo, KP);
                    wmma::load_matrix_sync(al[i], sAlo + mo, KP);
                }
                #pragma unroll
                for (int j = 0; j < 5; j++) {
                    wmma::fragment<wmma::matrix_b, 16, 16, 16, __nv_bfloat16, wmma::col_major> bh, bl;
                    const int no = (wn * 80 + j * 16) * KP + kk;
                    wmma::load_matrix_sync(bh, sWhi + no, KP);
                    wmma::load_matrix_sync(bl, sWlo + no, KP);
                    #pragma unroll
                    for (int i = 0; i < 2; i++) {
                        wmma::mma_sync(acc[i][j], ah[i], bh, acc[i][j]);
                        wmma::mma_sync(acc[i][j], ah[i], bl, acc[i][j]);
                        wmma::mma_sync(acc[i][j], al[i], bh, acc[i][j]);
                    }
                }
            }
        }

        if (t + 1 < NKT) {
            convert_a(aR, b ^ 1);
            if (t + 2 < NKT) {
                const float* ap = aptr + (size_t)(t + 2) * GBK;
                #pragma unroll
                for (int q = 0; q < 4; q++) aR[q] = ((const float4*)ap)[q];
            }
            asm volatile("cp.async.wait_group 0;");
        }
        __syncthreads();
    }

    float* ep = (float*)smem;   // 128 x 160
    #pragma unroll
    for (int i = 0; i < 2; i++)
        #pragma unroll
        for (int j = 0; j < 5; j++)
            wmma::store_matrix_sync(ep + (wm * 32 + i * 16) * 160 + wn * 80 + j * 16,
                                    acc[i][j], 160, wmma::mem_row_major);
    __syncthreads();

    const float pa = prelu_a[0];
    float* art = P_ART;
    for (int e = tid; e < GBM * GBN; e += 256) {
        int m = e / GBN, n = e % GBN;
        int gn = n0 + n;
        if (gn < Dn) {
            float v = ep[e] + bias[gn];
            v = (v > 0.f) ? v : pa * v;
            art[(size_t)(m0 + m) * Dn + gn] = v;
        }
    }
}

// ---------------------------------------------------------------------------
// Kernel 2: pooling, compacted words + float4 gather -> bf16 hi/lo [4096,320]
// ---------------------------------------------------------------------------
__global__ __launch_bounds__(128) void pool_kernel(
    const int* __restrict__ nodes_idx,
    const int* __restrict__ nmask)
{
    __shared__ int   s_tmp_idx[NWn];
    __shared__ int   s_tmp_msk[NWn];
    __shared__ int   s_off[NWn];
    __shared__ int   s_cw;
    __shared__ float s_inv;

    const int node = blockIdx.x;
    const int b    = node >> 8;
    const int tid  = threadIdx.x;

    if (tid < NWn) {
        int base = node * NWn + tid;
        s_tmp_idx[tid] = nodes_idx[base];
        s_tmp_msk[tid] = nmask[base];
    }
    __syncthreads();
    if (tid == 0) {
        int cw = 0;
        #pragma unroll
        for (int w = 0; w < NWn; w++)
            if (s_tmp_msk[w]) s_off[cw++] = s_tmp_idx[w] * (Dn / 4);
        s_cw = cw;
        s_inv = 1.0f / fmaxf((float)cw, 1.0f);
    }
    __syncthreads();

    const float4* art4 = (const float4*)(P_ART + (size_t)b * Ln * Dn);
    __nv_bfloat16* phi = P_PHI + (size_t)node * KPH;
    __nv_bfloat16* plo = P_PLO + (size_t)node * KPH;
    const int cw = s_cw;
    const float inv = s_inv;

    if (tid < Dn / 4) {
        float4 s = make_float4(0.f, 0.f, 0.f, 0.f);
        #pragma unroll 5
        for (int j = 0; j < cw; j++) {
            float4 v = art4[s_off[j] + tid];
            s.x += v.x; s.y += v.y; s.z += v.z; s.w += v.w;
        }
        s.x *= inv; s.y *= inv; s.z *= inv; s.w *= inv;
        uint32_t h01, l01, h23, l23;
        split2(s.x, s.y, h01, l01);
        split2(s.z, s.w, h23, l23);
        *(uint2*)(phi + tid * 4) = make_uint2(h01, h23);
        *(uint2*)(plo + tid * 4) = make_uint2(l01, l23);
    } else if (tid < KPH / 4) {
        *(uint2*)(phi + tid * 4) = make_uint2(0u, 0u);
        *(uint2*)(plo + tid * 4) = make_uint2(0u, 0u);
    }
}

// ---------------------------------------------------------------------------
// Kernel 3: head GEMM, M-tile 64, 128 CTAs, 3-buffer ring (2 stages in flight)
// h = relu(pooled·W1^T + b1); W2-dot fused into epilogue partial.
// ---------------------------------------------------------------------------
#define HASUB 5120                  // 64*40*2
#define HBSUB 10240                 // 128*40*2
#define HSM_A 0
#define HSM_B (6 * HASUB)           // 30720
#define SMEMG2 (HSM_B + 6 * HBSUB)  // 92160 (epilogue 64x128 f32 = 32768 overlays)
#define NKT2 (KPH / 32)             // 10

__global__ __launch_bounds__(256) void head_gemm_kernel(
    const float* __restrict__ b1,
    const float* __restrict__ W2)
{
    extern __shared__ char smem[];
    const uint32_t sb = smem_u32(smem);
    const int tid = threadIdx.x;
    const int wid = tid >> 5;
    const int m0 = blockIdx.y * 64;
    const int n0 = blockIdx.x * 128;
    const int wm = wid >> 1;              // 0..3 -> 16-row slices
    const int wn = wid & 1;               // 0..1 -> 64-col slices

    wmma::fragment<wmma::accumulator, 16, 16, 16, float> acc[4];
    #pragma unroll
    for (int j = 0; j < 4; j++) wmma::fill_fragment(acc[j], 0.0f);

    auto cp_stage = [&](int t) {
        const int k0 = t * 32;
        const int buf = t % 3;
        #pragma unroll
        for (int hl = 0; hl < 2; hl++) {
            const __nv_bfloat16* srcA = hl ? P_PLO : P_PHI;
            const __nv_bfloat16* srcB = hl ? P_W1LO : P_W1HI;
            uint32_t dA = sb + HSM_A + (uint32_t)((buf * 2 + hl) * HASUB);
            uint32_t dB = sb + HSM_B + (uint32_t)((buf * 2 + hl) * HBSUB);
            {   // A: 64 rows x 4 segs = 256 chunks
                int row = tid >> 2, seg = tid & 3;
                cp_async16(dA + (uint32_t)(row * (KP * 2) + seg * 16),
                           srcA + (size_t)(m0 + row) * KPH + k0 + seg * 8);
            }
            #pragma unroll
            for (int r = 0; r < 2; r++) {   // B: 128 rows x 4 segs = 512 chunks
                int i = tid + r * 256;
                int row = i >> 2, seg = i & 3;
                cp_async16(dB + (uint32_t)(row * (KP * 2) + seg * 16),
                           srcB + (size_t)(n0 + row) * KPH + k0 + seg * 8);
            }
        }
        asm volatile("cp.async.commit_group;");
    };

    // prologue: 2 stages in flight
    cp_stage(0);
    cp_stage(1);

    for (int t = 0; t < NKT2; t++) {
        if (t + 1 < NKT2) asm volatile("cp.async.wait_group 1;");  // stage t resident
        else              asm volatile("cp.async.wait_group 0;");
        __syncthreads();

        const int buf = t % 3;
        {
            const __nv_bfloat16* sAhi = (const __nv_bfloat16*)(smem + HSM_A + (buf * 2 + 0) * HASUB);
            const __nv_bfloat16* sAlo = (const __nv_bfloat16*)(smem + HSM_A + (buf * 2 + 1) * HASUB);
            const __nv_bfloat16* sBhi = (const __nv_bfloat16*)(smem + HSM_B + (buf * 2 + 0) * HBSUB);
            const __nv_bfloat16* sBlo = (const __nv_bfloat16*)(smem + HSM_B + (buf * 2 + 1) * HBSUB);
            #pragma unroll
            for (int kk = 0; kk < 32; kk += 16) {
                wmma::fragment<wmma::matrix_a, 16, 16, 16, __nv_bfloat16, wmma::row_major> ah, al;
                const int mo = (wm * 16) * KP + kk;
                wmma::load_matrix_sync(ah, sAhi + mo, KP);
                wmma::load_matrix_sync(al, sAlo + mo, KP);
                #pragma unroll
                for (int j = 0; j < 4; j++) {
                    wmma::fragment<wmma::matrix_b, 16, 16, 16, __nv_bfloat16, wmma::col_major> bh, bl;
                    const int no = (wn * 64 + j * 16) * KP + kk;
                    wmma::load_matrix_sync(bh, sBhi + no, KP);
                    wmma::load_matrix_sync(bl, sBlo + no, KP);
                    wmma::mma_sync(acc[j], ah, bh, acc[j]);
                    wmma::mma_sync(acc[j], ah, bl, acc[j]);
                    wmma::mma_sync(acc[j], al, bh, acc[j]);
                }
            }
        }
        // issue stage t+2 (its buffer held stage t-1, which all warps finished
        // before this iteration's __syncthreads)
        if (t + 2 < NKT2) cp_stage(t + 2);
        __syncthreads();
    }

    // epilogue: partial[m] = sum_n relu(h + b1) * W2 over this 128-col tile
    float* ep = (float*)smem;   // 64 x 128
    #pragma unroll
    for (int j = 0; j < 4; j++)
        wmma::store_matrix_sync(ep + (wm * 16) * 128 + wn * 64 + j * 16,
                                acc[j], 128, wmma::mem_row_major);
    __syncthreads();

    const int warp = tid >> 5, lane = tid & 31;
    float* part = P_PART + (size_t)blockIdx.x * NODES;
    for (int r = warp; r < 64; r += 8) {
        float s = 0.f;
        #pragma unroll
        for (int q = 0; q < 4; q++) {
            int n = lane + q * 32;
            float v = fmaxf(ep[r * 128 + n] + b1[n0 + n], 0.f);
            s += v * W2[n0 + n];
        }
        #pragma unroll
        for (int o = 16; o > 0; o >>= 1) s += __shfl_down_sync(0xffffffffu, s, o);
        if (lane == 0) part[m0 + r] = s;
    }
}

// ---------------------------------------------------------------------------
// Kernel 4: out[n] = part0[n] + part1[n] + b2
// ---------------------------------------------------------------------------
__global__ __launch_bounds__(256) void final_kernel(
    const float* __restrict__ b2, float* __restrict__ out)
{
    int n = blockIdx.x * 256 + threadIdx.x;
    if (n < NODES) out[n] = P_PART[n] + P_PART[NODES + n] + b2[0];
}

// ---------------------------------------------------------------------------
extern "C" void kernel_launch(void* const* d_in, const int* in_sizes, int n_in,
                              void* d_out, int out_size)
{
    const float* articles  = (const float*)d_in[0];
    const int*   nodes_idx = (const int*)  d_in[1];
    const int*   nmask     = (const int*)  d_in[2];
    // d_in[3], d_in[4] (relations) unused: reference discards edges
    const float* W_bert    = (const float*)d_in[5];
    const float* b_bert    = (const float*)d_in[6];
    const float* prelu_a   = (const float*)d_in[7];
    const float* W1        = (const float*)d_in[8];
    const float* b1        = (const float*)d_in[9];
    const float* W2        = (const float*)d_in[10];
    const float* b2        = (const float*)d_in[11];
    float*       out       = (float*)d_out;

    cudaFuncSetAttribute(gemm_fused3_kernel,
                         cudaFuncAttributeMaxDynamicSharedMemorySize, SMEMG);
    cudaFuncSetAttribute(head_gemm_kernel,
                         cudaFuncAttributeMaxDynamicSharedMemorySize, SMEMG2);

    // Stage 0: both weight splits in one launch
    split_weights_kernel<<<(NWP4 + NW1P4 + 255) / 256, 256>>>(W_bert, W1);

    // Stage 1: projection GEMM (branch-free R11 config), one wave
    dim3 gridG(NPAD / GBN, Mtot / GBM);   // (2, 64)
    gemm_fused3_kernel<<<gridG, 256, SMEMG>>>(articles, b_bert, prelu_a);

    // Stage 2: pooling (compacted + float4) -> bf16 hi/lo
    pool_kernel<<<NODES, 128>>>(nodes_idx, nmask);

    // Stage 3: head GEMM, 128 CTAs, 3-buffer pipeline, fused W2 partials
    dim3 gridH(Hn / 128, NODES / 64);     // (2, 64)
    head_gemm_kernel<<<gridH, 256, SMEMG2>>>(b1, W2);

    // Stage 4: combine partials
    final_kernel<<<(NODES + 255) / 256, 256>>>(b2, out);
}